// round 11
// baseline (speedup 1.0000x reference)
#include <cuda_runtime.h>
#include <cstdint>

// ============================ helpers ============================
__device__ __forceinline__ uint32_t smem_u32(const void* p) {
    uint32_t a;
    asm("{ .reg .u64 t; cvta.to.shared.u64 t, %1; cvt.u32.u64 %0, t; }" : "=r"(a) : "l"(p));
    return a;
}
__device__ __forceinline__ unsigned short f2bf(float f) {
    unsigned short r; asm("cvt.rn.bf16.f32 %0, %1;" : "=h"(r) : "f"(f)); return r;
}
__device__ __forceinline__ float bf2f(unsigned short u) {
    return __uint_as_float(((uint32_t)u) << 16);
}
__device__ __forceinline__ uint32_t packbf(float a, float b) {
    uint32_t r; asm("cvt.rn.bf16x2.f32 %0, %1, %2;" : "=r"(r) : "f"(b), "f"(a)); return r;
}

#define LDM4(r, addr) \
    asm volatile("ldmatrix.sync.aligned.m8n8.x4.shared.b16 {%0,%1,%2,%3}, [%4];" \
        : "=r"((r)[0]), "=r"((r)[1]), "=r"((r)[2]), "=r"((r)[3]) : "r"(addr))

#define LDM4T(r, addr) \
    asm volatile("ldmatrix.sync.aligned.m8n8.x4.trans.shared.b16 {%0,%1,%2,%3}, [%4];" \
        : "=r"((r)[0]), "=r"((r)[1]), "=r"((r)[2]), "=r"((r)[3]) : "r"(addr))

#define MMA_BF16(c, a, b0, b1) \
    asm volatile("mma.sync.aligned.m16n8k16.row.col.f32.bf16.bf16.f32 " \
        "{%0,%1,%2,%3}, {%4,%5,%6,%7}, {%8,%9}, {%0,%1,%2,%3};" \
        : "+f"((c)[0]), "+f"((c)[1]), "+f"((c)[2]), "+f"((c)[3]) \
        : "r"((a)[0]), "r"((a)[1]), "r"((a)[2]), "r"((a)[3]), "r"(b0), "r"(b1))

#define CP_COMMIT() asm volatile("cp.async.commit_group;" ::: "memory")
#define CP_WAIT0()  asm volatile("cp.async.wait_group 0;" ::: "memory")
#define CP_WAIT4()  asm volatile("cp.async.wait_group 4;" ::: "memory")
__device__ __forceinline__ void cp16(uint32_t dst_smem, const void* src) {
    asm volatile("cp.async.cg.shared.global [%0], [%1], 16;"
        :: "r"(dst_smem), "l"(__cvta_generic_to_global(src)) : "memory");
}

// ============================ constants ============================
constexpr int WN  = 49;
constexpr int D   = 128;
constexpr float SCALE = 0.17677669529663687f;

// prepacked weights: 8 chunks (6 qkv + 2 wout), each [hi 18432 | lo 18432]
// layout per half: k (0..127)*144 + n_local (0..63)*2
__device__ unsigned char g_wpk[8][36864];

// fused-kernel smem layout (bytes); all token buffers [64 r][272]
constexpr int F_AH   = 0;
constexpr int F_AL   = 17408;
constexpr int F_QH   = 34816;
constexpr int F_QL   = 52224;
constexpr int F_KH   = 69632;    // K row-major now
constexpr int F_KL   = 87040;
constexpr int F_VH   = 104448;
constexpr int F_VL   = 121856;
constexpr int F_B    = 139264;   // 2 chunk slots x [hi|lo] 36864
constexpr int F_BIAS = 212992;   // 676 floats
constexpr int F_TOTAL = 215696;

// ======================= weight prepack kernel =======================
__global__ void prepack_w(const float* __restrict__ wqkv,
                          const float* __restrict__ wout)
{
    int idx = blockIdx.x * 256 + threadIdx.x;
    if (idx < 128 * 384) {
        int k = idx / 384, n = idx - (idx / 384) * 384;
        float v = wqkv[idx];
        unsigned short h = f2bf(v), l = f2bf(v - bf2f(h));
        int c = n >> 6, nn = n & 63;
        *(unsigned short*)(g_wpk[c] + k * 144 + nn * 2) = h;
        *(unsigned short*)(g_wpk[c] + 18432 + k * 144 + nn * 2) = l;
    } else if (idx < 128 * 384 + 128 * 128) {
        int i2 = idx - 128 * 384;
        int k = i2 >> 7, n = i2 & 127;
        float v = wout[i2];
        unsigned short h = f2bf(v), l = f2bf(v - bf2f(h));
        int c = 6 + (n >> 6), nn = n & 63;
        *(unsigned short*)(g_wpk[c] + k * 144 + nn * 2) = h;
        *(unsigned short*)(g_wpk[c] + 18432 + k * 144 + nn * 2) = l;
    }
}

// ============ split-bf16 pair store (hi + residual lo) ============
__device__ __forceinline__ void store_sp(char* smc, int baseH, int off,
                                         float a, float b) {
    uint32_t hp = packbf(a, b);
    float ra = a - __uint_as_float(hp << 16);
    float rb = b - __uint_as_float(hp & 0xFFFF0000u);
    *(uint32_t*)(smc + baseH + off) = hp;
    *(uint32_t*)(smc + baseH + 17408 + off) = packbf(ra, rb);
}

// issue one QKV stage's W (2 chunks) as 8 k-slab commit groups
__device__ __forceinline__ void issue_stage(uint32_t sb, int s, int t) {
    const int c0 = 2 * s;
#pragma unroll
    for (int g = 0; g < 8; g++) {
        for (int i = t; i < 576; i += 512) {
            int b = i / 144;                 // 0..3: slot(2) x half(2)
            int off = (i - b * 144) * 16;
            const unsigned char* src =
                g_wpk[c0 + (b >> 1)] + (b & 1) * 18432 + g * 2304 + off;
            cp16(sb + F_B + (b >> 1) * 36864 + (b & 1) * 18432 + g * 2304 + off,
                 src);
        }
        CP_COMMIT();
    }
}

__device__ __forceinline__ void issue_wout(uint32_t sb, int t) {
    for (int i = t; i < 4608; i += 512) {
        int b = i / 1152;                    // 0..3
        int off = (i - b * 1152) * 16;
        const unsigned char* src = g_wpk[6 + (b >> 1)] + (b & 1) * 18432 + off;
        cp16(sb + F_B + (b >> 1) * 36864 + (b & 1) * 18432 + off, src);
    }
    CP_COMMIT();
}

// ========================= fused window kernel =========================
__global__ __launch_bounds__(512, 1)
void fused_win(const float* __restrict__ x, const float* __restrict__ btab,
               float* __restrict__ out)
{
    extern __shared__ char smc[];
    const uint32_t sb = smem_u32(smc);
    const int t = threadIdx.x;
    const size_t win = blockIdx.x;
    const float* xw = x + win * (size_t)(WN * D);
    float* bias_s = (float*)(smc + F_BIAS);

    const int w     = t >> 5;        // 0..15
    const int lane  = t & 31;
    const int wm    = w & 3;         // 16-row m-tile
    const int wn    = w >> 2;        // 32-col n-tile (of 128)
    const int lrow  = lane & 15;
    const int lhalf = lane >> 4;
    const int qrow  = lane >> 2;
    const int qt2   = (lane & 3) << 1;

    // stage-0 W prefetch first
    issue_stage(sb, 0, t);

    // zero A (pads must be 0), stage bias
    uint4 z4 = make_uint4(0u, 0u, 0u, 0u);
    for (int i = t; i < 2176; i += 512) ((uint4*)smc)[i] = z4;
    for (int i = t; i < 676; i += 512) bias_s[i] = btab[i];

    // stage x (49x128 f32) -> split-bf16 A
    for (int idx4 = t; idx4 < 1568; idx4 += 512) {
        int r  = idx4 >> 5;
        int c4 = (idx4 & 31) << 2;
        float4 v = *(const float4*)(xw + r * D + c4);
        float vv[4] = {v.x, v.y, v.z, v.w};
        unsigned short hh[4], ll[4];
#pragma unroll
        for (int e = 0; e < 4; e++) {
            hh[e] = f2bf(vv[e]); ll[e] = f2bf(vv[e] - bf2f(hh[e]));
        }
        int off = r * 272 + c4 * 2;
        *(uint2*)(smc + F_AH + off) = make_uint2(
            (uint32_t)hh[0] | ((uint32_t)hh[1] << 16),
            (uint32_t)hh[2] | ((uint32_t)hh[3] << 16));
        *(uint2*)(smc + F_AL + off) = make_uint2(
            (uint32_t)ll[0] | ((uint32_t)ll[1] << 16),
            (uint32_t)ll[2] | ((uint32_t)ll[3] << 16));
    }
    __syncthreads();

    // ============ Phase 1: QKV GEMM, 3 stages of 128 cols ============
    const uint32_t Bslot = sb + F_B + (wn >> 1) * 36864;
    const int ncl = (wn & 1) * 32;

#pragma unroll 1
    for (int s = 0; s < 3; s++) {
        float acc[4][4];
#pragma unroll
        for (int j = 0; j < 4; j++)
#pragma unroll
            for (int e = 0; e < 4; e++) acc[j][e] = 0.f;

#pragma unroll 1
        for (int hv = 0; hv < 2; hv++) {
            if (hv == 0) { CP_WAIT4(); } else { CP_WAIT0(); }
            __syncthreads();
#pragma unroll
            for (int kq = 0; kq < 4; kq++) {
                const int kt = hv * 4 + kq;
                uint32_t ah[4], al[4], bh[2][4], bl[2][4];
                uint32_t aoff = (uint32_t)((wm * 16 + lrow) * 272
                                           + kt * 32 + lhalf * 16);
                LDM4(ah, sb + F_AH + aoff);
                LDM4(al, sb + F_AL + aoff);
#pragma unroll
                for (int nt = 0; nt < 2; nt++) {
                    uint32_t boff = (uint32_t)((kt * 16 + lrow) * 144
                                               + (ncl + nt * 16) * 2 + lhalf * 16);
                    LDM4T(bh[nt], Bslot + boff);
                    LDM4T(bl[nt], Bslot + 18432 + boff);
                }
#pragma unroll
                for (int j = 0; j < 4; j++)
                    MMA_BF16(acc[j], ah, bh[j >> 1][2 * (j & 1)],
                             bh[j >> 1][2 * (j & 1) + 1]);
#pragma unroll
                for (int j = 0; j < 4; j++)
                    MMA_BF16(acc[j], ah, bl[j >> 1][2 * (j & 1)],
                             bl[j >> 1][2 * (j & 1) + 1]);
#pragma unroll
                for (int j = 0; j < 4; j++)
                    MMA_BF16(acc[j], al, bh[j >> 1][2 * (j & 1)],
                             bh[j >> 1][2 * (j & 1) + 1]);
            }
        }
        __syncthreads();                 // all warps done reading W_s
        if (s < 2) issue_stage(sb, s + 1, t);
        else       issue_wout(sb, t);

        // epilogue -> Q (s=0) / K (s=1, row-major) / V (s=2), split bf16
        const int baseH = (s == 0) ? F_QH : (s == 1) ? F_KH : F_VH;
        const int r0 = wm * 16 + qrow, r1 = r0 + 8;
#pragma unroll
        for (int j = 0; j < 4; j++) {
            int col = wn * 32 + j * 8 + qt2;
            store_sp(smc, baseH, r0 * 272 + col * 2, acc[j][0], acc[j][1]);
            store_sp(smc, baseH, r1 * 272 + col * 2, acc[j][2], acc[j][3]);
        }
    }
    __syncthreads();                     // Q/K/V visible

    // ================= Phase 2: attention, 1 task per warp =================
    {
        const int h  = w >> 2;
        const int i0 = (w & 3) << 4;

        float sc[7][4];
#pragma unroll
        for (int nt = 0; nt < 7; nt++)
#pragma unroll
            for (int e = 0; e < 4; e++) sc[nt][e] = 0.f;

#pragma unroll
        for (int kt = 0; kt < 2; kt++) {
            uint32_t ah[4], al[4], bh[4][4], bl[4][4];
            uint32_t coff = (uint32_t)((h * 32 + kt * 16) * 2 + lhalf * 16);
            uint32_t aoff = (uint32_t)((i0 + lrow) * 272) + coff;
            LDM4(ah, sb + F_QH + aoff);
            LDM4(al, sb + F_QL + aoff);
#pragma unroll
            for (int g = 0; g < 4; g++) {
                uint32_t boff = (uint32_t)((g * 16 + lrow) * 272) + coff;
                LDM4(bh[g], sb + F_KH + boff);   // K row-major, non-trans
                LDM4(bl[g], sb + F_KL + boff);
            }
#pragma unroll
            for (int nt = 0; nt < 7; nt++)
                MMA_BF16(sc[nt], ah, bh[nt >> 1][nt & 1], bh[nt >> 1][2 + (nt & 1)]);
#pragma unroll
            for (int nt = 0; nt < 7; nt++)
                MMA_BF16(sc[nt], ah, bl[nt >> 1][nt & 1], bl[nt >> 1][2 + (nt & 1)]);
#pragma unroll
            for (int nt = 0; nt < 7; nt++)
                MMA_BF16(sc[nt], al, bh[nt >> 1][nt & 1], bh[nt >> 1][2 + (nt & 1)]);
        }

        // softmax in fragments (unnormalized)
        const int r0 = i0 + qrow, r1 = r0 + 8;
        const int gi0 = r0 / 7, gj0 = r0 - 7 * gi0;
        const int gi1 = r1 / 7, gj1 = r1 - 7 * gi1;
        float rs0 = 0.f, rs1 = 0.f;
#pragma unroll
        for (int nt = 0; nt < 7; nt++) {
#pragma unroll
            for (int e = 0; e < 4; e++) {
                int j = nt * 8 + qt2 + (e & 1);
                int r = (e < 2) ? r0 : r1;
                float ev = 0.f;
                if (r < 49 && j < 49) {
                    int gj2 = j / 7;
                    int gjj = j - 7 * gj2;
                    int gi = (e < 2) ? gi0 : gi1;
                    int gj = (e < 2) ? gj0 : gj1;
                    int bidx = ((gi - gj2 + 6) * 13 + (gj - gjj + 6)) * 4 + h;
                    ev = __expf(sc[nt][e] * SCALE + bias_s[bidx]);
                }
                sc[nt][e] = ev;
                if (e < 2) rs0 += ev; else rs1 += ev;
            }
        }
        rs0 += __shfl_xor_sync(0xFFFFFFFFu, rs0, 1);
        rs0 += __shfl_xor_sync(0xFFFFFFFFu, rs0, 2);
        rs1 += __shfl_xor_sync(0xFFFFFFFFu, rs1, 1);
        rs1 += __shfl_xor_sync(0xFFFFFFFFu, rs1, 2);
        const float inv0 = (r0 < 49) ? 1.f / rs0 : 0.f;
        const float inv1 = (r1 < 49) ? 1.f / rs1 : 0.f;

        // O = P V (P built in-register, split)
        float oc[4][4];
#pragma unroll
        for (int nt = 0; nt < 4; nt++)
#pragma unroll
            for (int e = 0; e < 4; e++) oc[nt][e] = 0.f;

#pragma unroll
        for (int kt2 = 0; kt2 < 4; kt2++) {
            const int lo = 2 * kt2, hi = lo + 1;
            float pe[8];
            pe[0] = sc[lo][0]; pe[1] = sc[lo][1];
            pe[2] = sc[lo][2]; pe[3] = sc[lo][3];
            if (hi < 7) {
                pe[4] = sc[hi][0]; pe[5] = sc[hi][1];
                pe[6] = sc[hi][2]; pe[7] = sc[hi][3];
            } else {
                pe[4] = pe[5] = pe[6] = pe[7] = 0.f;
            }
            uint32_t ph[4], pl[4];
#pragma unroll
            for (int g = 0; g < 4; g++) {
                float a = pe[2 * g], b = pe[2 * g + 1];
                uint32_t hp = packbf(a, b);
                float ra = a - __uint_as_float(hp << 16);
                float rb = b - __uint_as_float(hp & 0xFFFF0000u);
                ph[g] = hp;
                pl[g] = packbf(ra, rb);
            }
            uint32_t vh[2][4], vl[2][4];
#pragma unroll
            for (int g = 0; g < 2; g++) {
                uint32_t voff = (uint32_t)((kt2 * 16 + lrow) * 272
                                           + h * 64 + g * 32 + lhalf * 16);
                LDM4T(vh[g], sb + F_VH + voff);
                LDM4T(vl[g], sb + F_VL + voff);
            }
#pragma unroll
            for (int nt = 0; nt < 4; nt++)
                MMA_BF16(oc[nt], ph, vh[nt >> 1][2 * (nt & 1)],
                         vh[nt >> 1][2 * (nt & 1) + 1]);
#pragma unroll
            for (int nt = 0; nt < 4; nt++)
                MMA_BF16(oc[nt], ph, vl[nt >> 1][2 * (nt & 1)],
                         vl[nt >> 1][2 * (nt & 1) + 1]);
#pragma unroll
            for (int nt = 0; nt < 4; nt++)
                MMA_BF16(oc[nt], pl, vh[nt >> 1][2 * (nt & 1)],
                         vh[nt >> 1][2 * (nt & 1) + 1]);
        }

        // store attn-out (normalized) into A buffer (split bf16)
#pragma unroll
        for (int nt = 0; nt < 4; nt++) {
            int col = h * 32 + nt * 8 + qt2;
            if (r0 < 49)
                store_sp(smc, F_AH, r0 * 272 + col * 2,
                         oc[nt][0] * inv0, oc[nt][1] * inv0);
            if (r1 < 49)
                store_sp(smc, F_AH, r1 * 272 + col * 2,
                         oc[nt][2] * inv1, oc[nt][3] * inv1);
        }
    }

    CP_WAIT0();
    __syncthreads();                 // Wout in + attn-out visible

    // ================= Phase 3: out-proj, single 128-col stage =================
    {
        float acc[4][4];
#pragma unroll
        for (int j = 0; j < 4; j++)
#pragma unroll
            for (int e = 0; e < 4; e++) acc[j][e] = 0.f;

#pragma unroll
        for (int kt = 0; kt < 8; kt++) {
            uint32_t ah[4], al[4], bh[2][4], bl[2][4];
            uint32_t aoff = (uint32_t)((wm * 16 + lrow) * 272
                                       + kt * 32 + lhalf * 16);
            LDM4(ah, sb + F_AH + aoff);
            LDM4(al, sb + F_AL + aoff);
#pragma unroll
            for (int nt = 0; nt < 2; nt++) {
                uint32_t boff = (uint32_t)((kt * 16 + lrow) * 144
                                           + (ncl + nt * 16) * 2 + lhalf * 16);
                LDM4T(bh[nt], Bslot + boff);
                LDM4T(bl[nt], Bslot + 18432 + boff);
            }
#pragma unroll
            for (int j = 0; j < 4; j++)
                MMA_BF16(acc[j], ah, bh[j >> 1][2 * (j & 1)],
                         bh[j >> 1][2 * (j & 1) + 1]);
#pragma unroll
            for (int j = 0; j < 4; j++)
                MMA_BF16(acc[j], ah, bl[j >> 1][2 * (j & 1)],
                         bl[j >> 1][2 * (j & 1) + 1]);
#pragma unroll
            for (int j = 0; j < 4; j++)
                MMA_BF16(acc[j], al, bh[j >> 1][2 * (j & 1)],
                         bh[j >> 1][2 * (j & 1) + 1]);
        }

        const int r0 = wm * 16 + qrow, r1 = r0 + 8;
#pragma unroll
        for (int j = 0; j < 4; j++) {
            int col = wn * 32 + j * 8 + qt2;
            if (r0 < 49)
                *(float2*)(out + (win * WN + r0) * (size_t)D + col) =
                    make_float2(acc[j][0], acc[j][1]);
            if (r1 < 49)
                *(float2*)(out + (win * WN + r1) * (size_t)D + col) =
                    make_float2(acc[j][2], acc[j][3]);
        }
    }
}

// ============================== launcher ==============================
extern "C" void kernel_launch(void* const* d_in, const int* in_sizes, int n_in,
                              void* d_out, int out_size) {
    const float* x    = (const float*)d_in[0];
    const float* wqkv = (const float*)d_in[1];
    const float* wout = (const float*)d_in[2];
    const float* btab = (const float*)d_in[3];
    float* out = (float*)d_out;

    const int n_win = in_sizes[0] / (WN * D);

    cudaFuncSetAttribute(fused_win,
                         cudaFuncAttributeMaxDynamicSharedMemorySize, F_TOTAL);

    prepack_w<<<256, 256>>>(wqkv, wout);
    fused_win<<<n_win, 512, F_TOTAL>>>(x, btab, out);
}

// round 12
// speedup vs baseline: 1.2226x; 1.2226x over previous
#include <cuda_runtime.h>
#include <cstdint>

// ============================ helpers ============================
__device__ __forceinline__ uint32_t smem_u32(const void* p) {
    uint32_t a;
    asm("{ .reg .u64 t; cvta.to.shared.u64 t, %1; cvt.u32.u64 %0, t; }" : "=r"(a) : "l"(p));
    return a;
}
__device__ __forceinline__ unsigned short f2bf(float f) {
    unsigned short r; asm("cvt.rn.bf16.f32 %0, %1;" : "=h"(r) : "f"(f)); return r;
}
__device__ __forceinline__ float bf2f(unsigned short u) {
    return __uint_as_float(((uint32_t)u) << 16);
}
__device__ __forceinline__ uint32_t packbf(float a, float b) {
    uint32_t r; asm("cvt.rn.bf16x2.f32 %0, %1, %2;" : "=r"(r) : "f"(b), "f"(a)); return r;
}

#define LDM4(r, addr) \
    asm volatile("ldmatrix.sync.aligned.m8n8.x4.shared.b16 {%0,%1,%2,%3}, [%4];" \
        : "=r"((r)[0]), "=r"((r)[1]), "=r"((r)[2]), "=r"((r)[3]) : "r"(addr))

#define LDM4T(r, addr) \
    asm volatile("ldmatrix.sync.aligned.m8n8.x4.trans.shared.b16 {%0,%1,%2,%3}, [%4];" \
        : "=r"((r)[0]), "=r"((r)[1]), "=r"((r)[2]), "=r"((r)[3]) : "r"(addr))

#define MMA_BF16(c, a, b0, b1) \
    asm volatile("mma.sync.aligned.m16n8k16.row.col.f32.bf16.bf16.f32 " \
        "{%0,%1,%2,%3}, {%4,%5,%6,%7}, {%8,%9}, {%0,%1,%2,%3};" \
        : "+f"((c)[0]), "+f"((c)[1]), "+f"((c)[2]), "+f"((c)[3]) \
        : "r"((a)[0]), "r"((a)[1]), "r"((a)[2]), "r"((a)[3]), "r"(b0), "r"(b1))

#define CP_COMMIT() asm volatile("cp.async.commit_group;" ::: "memory")
#define CP_WAIT0()  asm volatile("cp.async.wait_group 0;" ::: "memory")
#define CP_WAIT4()  asm volatile("cp.async.wait_group 4;" ::: "memory")
__device__ __forceinline__ void cp16(uint32_t dst_smem, const void* src) {
    asm volatile("cp.async.cg.shared.global [%0], [%1], 16;"
        :: "r"(dst_smem), "l"(__cvta_generic_to_global(src)) : "memory");
}

// ============================ constants ============================
constexpr int WN  = 49;
constexpr int D   = 128;
constexpr float SCALE = 0.17677669529663687f;

// prepacked weights: 8 chunks (6 qkv + 2 wout), each [hi 18432 | lo 18432]
// per half: k(0..127)*144 + n_local(0..63)*2
__device__ unsigned char g_wpk[8][36864];

// fused-kernel smem layout (bytes)
constexpr int F_AH   = 0;        // x / attn-out hi [64][272]
constexpr int F_AL   = 17408;    // lo
constexpr int F_Q    = 34816;    // q hi only [64][272]
constexpr int F_K    = 52224;    // k hi only, row-major [64][272]
constexpr int F_VH   = 69632;    // v hi [64][272]
constexpr int F_VL   = 87040;    // v lo
constexpr int F_B    = 104448;   // W region: 4 x 18432 quadrants
constexpr int F_BIAS = 178176;   // 676 floats
constexpr int F_TOTAL = 180880;

// ======================= weight prepack kernel =======================
__global__ void prepack_w(const float* __restrict__ wqkv,
                          const float* __restrict__ wout)
{
    int idx = blockIdx.x * 256 + threadIdx.x;
    if (idx < 128 * 384) {
        int k = idx / 384, n = idx - (idx / 384) * 384;
        float v = wqkv[idx];
        unsigned short h = f2bf(v), l = f2bf(v - bf2f(h));
        int c = n >> 6, nn = n & 63;
        *(unsigned short*)(g_wpk[c] + k * 144 + nn * 2) = h;
        *(unsigned short*)(g_wpk[c] + 18432 + k * 144 + nn * 2) = l;
    } else if (idx < 128 * 384 + 128 * 128) {
        int i2 = idx - 128 * 384;
        int k = i2 >> 7, n = i2 & 127;
        float v = wout[i2];
        unsigned short h = f2bf(v), l = f2bf(v - bf2f(h));
        int c = 6 + (n >> 6), nn = n & 63;
        *(unsigned short*)(g_wpk[c] + k * 144 + nn * 2) = h;
        *(unsigned short*)(g_wpk[c] + 18432 + k * 144 + nn * 2) = l;
    }
}

// ============ split-bf16 pair store (hi + residual lo) ============
__device__ __forceinline__ void store_sp(char* smc, int baseH, int off,
                                         float a, float b) {
    uint32_t hp = packbf(a, b);
    float ra = a - __uint_as_float(hp << 16);
    float rb = b - __uint_as_float(hp & 0xFFFF0000u);
    *(uint32_t*)(smc + baseH + off) = hp;
    *(uint32_t*)(smc + baseH + 17408 + off) = packbf(ra, rb);
}

// --- cp.async issuers ---
// q+k stages: hi halves of chunks 0..3 -> quadrants 0..3; 8 k-slab groups
__device__ __forceinline__ void issue_qk(uint32_t sb, int t) {
#pragma unroll
    for (int g = 0; g < 8; g++) {
        for (int i = t; i < 576; i += 512) {
            int b = i / 144;
            int off = (i - b * 144) * 16;
            cp16(sb + F_B + b * 18432 + g * 2304 + off,
                 g_wpk[b] + g * 2304 + off);
        }
        CP_COMMIT();
    }
}
// v stage: chunks 4,5 hi+lo; 8 k-slab groups
__device__ __forceinline__ void issue_s2(uint32_t sb, int t) {
#pragma unroll
    for (int g = 0; g < 8; g++) {
        for (int i = t; i < 576; i += 512) {
            int b = i / 144;
            int off = (i - b * 144) * 16;
            cp16(sb + F_B + (b >> 1) * 36864 + (b & 1) * 18432 + g * 2304 + off,
                 g_wpk[4 + (b >> 1)] + (b & 1) * 18432 + g * 2304 + off);
        }
        CP_COMMIT();
    }
}
// wout: chunks 6,7 hi+lo; 1 group (overlaps attention)
__device__ __forceinline__ void issue_wout(uint32_t sb, int t) {
    for (int i = t; i < 4608; i += 512) {
        int b = i / 1152;
        int off = (i - b * 1152) * 16;
        cp16(sb + F_B + (b >> 1) * 36864 + (b & 1) * 18432 + off,
             g_wpk[6 + (b >> 1)] + (b & 1) * 18432 + off);
    }
    CP_COMMIT();
}

// ========================= fused window kernel =========================
__global__ __launch_bounds__(512, 1)
void fused_win(const float* __restrict__ x, const float* __restrict__ btab,
               float* __restrict__ out)
{
    extern __shared__ char smc[];
    const uint32_t sb = smem_u32(smc);
    const int t = threadIdx.x;
    const size_t win = blockIdx.x;
    const float* xw = x + win * (size_t)(WN * D);
    float* bias_s = (float*)(smc + F_BIAS);

    const int w     = t >> 5;
    const int lane  = t & 31;
    const int wm    = w & 3;
    const int wn    = w >> 2;
    const int lrow  = lane & 15;
    const int lhalf = lane >> 4;
    const int qrow  = lane >> 2;
    const int qt2   = (lane & 3) << 1;

    issue_qk(sb, t);   // q+k weights (hi) for both stages, upfront

    // zero A (pads must be 0), stage bias
    uint4 z4 = make_uint4(0u, 0u, 0u, 0u);
    for (int i = t; i < 2176; i += 512) ((uint4*)smc)[i] = z4;
    for (int i = t; i < 676; i += 512) bias_s[i] = btab[i];

    // stage x (49x128 f32) -> split-bf16 A
    for (int idx4 = t; idx4 < 1568; idx4 += 512) {
        int r  = idx4 >> 5;
        int c4 = (idx4 & 31) << 2;
        float4 v = *(const float4*)(xw + r * D + c4);
        float vv[4] = {v.x, v.y, v.z, v.w};
        unsigned short hh[4], ll[4];
#pragma unroll
        for (int e = 0; e < 4; e++) {
            hh[e] = f2bf(vv[e]); ll[e] = f2bf(vv[e] - bf2f(hh[e]));
        }
        int off = r * 272 + c4 * 2;
        *(uint2*)(smc + F_AH + off) = make_uint2(
            (uint32_t)hh[0] | ((uint32_t)hh[1] << 16),
            (uint32_t)hh[2] | ((uint32_t)hh[3] << 16));
        *(uint2*)(smc + F_AL + off) = make_uint2(
            (uint32_t)ll[0] | ((uint32_t)ll[1] << 16),
            (uint32_t)ll[2] | ((uint32_t)ll[3] << 16));
    }
    __syncthreads();

    // ============ Phase 1a: q,k stages (single-pass bf16) ============
    const int ncl2 = ((wn & 1) * 32) * 2;   // byte col base within chunk
#pragma unroll 1
    for (int s = 0; s < 2; s++) {
        const uint32_t Bq = sb + F_B + s * 36864 + (wn >> 1) * 18432;
        float acc[4][4];
#pragma unroll
        for (int j = 0; j < 4; j++)
#pragma unroll
            for (int e = 0; e < 4; e++) acc[j][e] = 0.f;

#pragma unroll 1
        for (int hv = 0; hv < 2; hv++) {
            if (s == 0) {
                if (hv == 0) { CP_WAIT4(); } else { CP_WAIT0(); }
                __syncthreads();
            }
#pragma unroll
            for (int kq = 0; kq < 4; kq++) {
                const int kt = hv * 4 + kq;
                uint32_t ah[4], bh[2][4];
                uint32_t aoff = (uint32_t)((wm * 16 + lrow) * 272
                                           + kt * 32 + lhalf * 16);
                LDM4(ah, sb + F_AH + aoff);
#pragma unroll
                for (int nt = 0; nt < 2; nt++) {
                    uint32_t boff = (uint32_t)((kt * 16 + lrow) * 144
                                               + ncl2 + nt * 32 + lhalf * 16);
                    LDM4T(bh[nt], Bq + boff);
                }
#pragma unroll
                for (int j = 0; j < 4; j++)
                    MMA_BF16(acc[j], ah, bh[j >> 1][2 * (j & 1)],
                             bh[j >> 1][2 * (j & 1) + 1]);
            }
        }
        // epilogue: single-bf16 q (s=0) / k (s=1)
        const int base = (s == 0) ? F_Q : F_K;
        const int r0 = wm * 16 + qrow, r1 = r0 + 8;
#pragma unroll
        for (int j = 0; j < 4; j++) {
            int cb = (wn * 32 + j * 8 + qt2) * 2;
            *(uint32_t*)(smc + base + r0 * 272 + cb) = packbf(acc[j][0], acc[j][1]);
            *(uint32_t*)(smc + base + r1 * 272 + cb) = packbf(acc[j][2], acc[j][3]);
        }
    }
    __syncthreads();                 // B region fully consumed
    issue_s2(sb, t);

    // ============ Phase 1b: v stage (3-pass split) ============
    {
        const uint32_t Bslot = sb + F_B + (wn >> 1) * 36864;
        float acc[4][4];
#pragma unroll
        for (int j = 0; j < 4; j++)
#pragma unroll
            for (int e = 0; e < 4; e++) acc[j][e] = 0.f;

#pragma unroll 1
        for (int hv = 0; hv < 2; hv++) {
            if (hv == 0) { CP_WAIT4(); } else { CP_WAIT0(); }
            __syncthreads();
#pragma unroll
            for (int kq = 0; kq < 4; kq++) {
                const int kt = hv * 4 + kq;
                uint32_t ah[4], al[4], bh[2][4], bl[2][4];
                uint32_t aoff = (uint32_t)((wm * 16 + lrow) * 272
                                           + kt * 32 + lhalf * 16);
                LDM4(ah, sb + F_AH + aoff);
                LDM4(al, sb + F_AL + aoff);
#pragma unroll
                for (int nt = 0; nt < 2; nt++) {
                    uint32_t boff = (uint32_t)((kt * 16 + lrow) * 144
                                               + ncl2 + nt * 32 + lhalf * 16);
                    LDM4T(bh[nt], Bslot + boff);
                    LDM4T(bl[nt], Bslot + 18432 + boff);
                }
#pragma unroll
                for (int j = 0; j < 4; j++)
                    MMA_BF16(acc[j], ah, bh[j >> 1][2 * (j & 1)],
                             bh[j >> 1][2 * (j & 1) + 1]);
#pragma unroll
                for (int j = 0; j < 4; j++)
                    MMA_BF16(acc[j], ah, bl[j >> 1][2 * (j & 1)],
                             bl[j >> 1][2 * (j & 1) + 1]);
#pragma unroll
                for (int j = 0; j < 4; j++)
                    MMA_BF16(acc[j], al, bh[j >> 1][2 * (j & 1)],
                             bh[j >> 1][2 * (j & 1) + 1]);
            }
        }
        __syncthreads();             // B consumed
        issue_wout(sb, t);

        // epilogue: split v
        const int r0 = wm * 16 + qrow, r1 = r0 + 8;
#pragma unroll
        for (int j = 0; j < 4; j++) {
            int off0 = r0 * 272 + (wn * 32 + j * 8 + qt2) * 2;
            int off1 = r1 * 272 + (wn * 32 + j * 8 + qt2) * 2;
            store_sp(smc, F_VH, off0, acc[j][0], acc[j][1]);
            store_sp(smc, F_VH, off1, acc[j][2], acc[j][3]);
        }
    }
    __syncthreads();                 // q/k/v visible

    // ================= Phase 2: attention, 1 task per warp =================
    {
        const int h  = w >> 2;
        const int i0 = (w & 3) << 4;

        float sc[7][4];
#pragma unroll
        for (int nt = 0; nt < 7; nt++)
#pragma unroll
            for (int e = 0; e < 4; e++) sc[nt][e] = 0.f;

        // S = q k^T, single-pass bf16
#pragma unroll
        for (int kt = 0; kt < 2; kt++) {
            uint32_t ah[4], bh[4][4];
            uint32_t coff = (uint32_t)((h * 32 + kt * 16) * 2 + lhalf * 16);
            LDM4(ah, sb + F_Q + (uint32_t)((i0 + lrow) * 272) + coff);
#pragma unroll
            for (int g = 0; g < 4; g++)
                LDM4(bh[g], sb + F_K + (uint32_t)((g * 16 + lrow) * 272) + coff);
#pragma unroll
            for (int nt = 0; nt < 7; nt++)
                MMA_BF16(sc[nt], ah, bh[nt >> 1][nt & 1], bh[nt >> 1][2 + (nt & 1)]);
        }

        // softmax in fragments (unnormalized)
        const int r0 = i0 + qrow, r1 = r0 + 8;
        const int gi0 = r0 / 7, gj0 = r0 - 7 * gi0;
        const int gi1 = r1 / 7, gj1 = r1 - 7 * gi1;
        float rs0 = 0.f, rs1 = 0.f;
#pragma unroll
        for (int nt = 0; nt < 7; nt++) {
#pragma unroll
            for (int e = 0; e < 4; e++) {
                int j = nt * 8 + qt2 + (e & 1);
                int r = (e < 2) ? r0 : r1;
                float ev = 0.f;
                if (r < 49 && j < 49) {
                    int gj2 = j / 7;
                    int gjj = j - 7 * gj2;
                    int gi = (e < 2) ? gi0 : gi1;
                    int gj = (e < 2) ? gj0 : gj1;
                    int bidx = ((gi - gj2 + 6) * 13 + (gj - gjj + 6)) * 4 + h;
                    ev = __expf(sc[nt][e] * SCALE + bias_s[bidx]);
                }
                sc[nt][e] = ev;
                if (e < 2) rs0 += ev; else rs1 += ev;
            }
        }
        rs0 += __shfl_xor_sync(0xFFFFFFFFu, rs0, 1);
        rs0 += __shfl_xor_sync(0xFFFFFFFFu, rs0, 2);
        rs1 += __shfl_xor_sync(0xFFFFFFFFu, rs1, 1);
        rs1 += __shfl_xor_sync(0xFFFFFFFFu, rs1, 2);
        const float inv0 = (r0 < 49) ? 1.f / rs0 : 0.f;
        const float inv1 = (r1 < 49) ? 1.f / rs1 : 0.f;

        // O = P V (split P in-register x split V)
        float oc[4][4];
#pragma unroll
        for (int nt = 0; nt < 4; nt++)
#pragma unroll
            for (int e = 0; e < 4; e++) oc[nt][e] = 0.f;

#pragma unroll
        for (int kt2 = 0; kt2 < 4; kt2++) {
            const int lo = 2 * kt2, hi = lo + 1;
            float pe[8];
            pe[0] = sc[lo][0]; pe[1] = sc[lo][1];
            pe[2] = sc[lo][2]; pe[3] = sc[lo][3];
            if (hi < 7) {
                pe[4] = sc[hi][0]; pe[5] = sc[hi][1];
                pe[6] = sc[hi][2]; pe[7] = sc[hi][3];
            } else {
                pe[4] = pe[5] = pe[6] = pe[7] = 0.f;
            }
            uint32_t ph[4], pl[4];
#pragma unroll
            for (int g = 0; g < 4; g++) {
                float a = pe[2 * g], b = pe[2 * g + 1];
                uint32_t hp = packbf(a, b);
                float ra = a - __uint_as_float(hp << 16);
                float rb = b - __uint_as_float(hp & 0xFFFF0000u);
                ph[g] = hp;
                pl[g] = packbf(ra, rb);
            }
            uint32_t vh[2][4], vl[2][4];
#pragma unroll
            for (int g = 0; g < 2; g++) {
                uint32_t voff = (uint32_t)((kt2 * 16 + lrow) * 272
                                           + h * 64 + g * 32 + lhalf * 16);
                LDM4T(vh[g], sb + F_VH + voff);
                LDM4T(vl[g], sb + F_VL + voff);
            }
#pragma unroll
            for (int nt = 0; nt < 4; nt++)
                MMA_BF16(oc[nt], ph, vh[nt >> 1][2 * (nt & 1)],
                         vh[nt >> 1][2 * (nt & 1) + 1]);
#pragma unroll
            for (int nt = 0; nt < 4; nt++)
                MMA_BF16(oc[nt], ph, vl[nt >> 1][2 * (nt & 1)],
                         vl[nt >> 1][2 * (nt & 1) + 1]);
#pragma unroll
            for (int nt = 0; nt < 4; nt++)
                MMA_BF16(oc[nt], pl, vh[nt >> 1][2 * (nt & 1)],
                         vh[nt >> 1][2 * (nt & 1) + 1]);
        }

        // store attn-out (normalized) into A buffer (split bf16)
#pragma unroll
        for (int nt = 0; nt < 4; nt++) {
            int col = h * 32 + nt * 8 + qt2;
            if (r0 < 49)
                store_sp(smc, F_AH, r0 * 272 + col * 2,
                         oc[nt][0] * inv0, oc[nt][1] * inv0);
            if (r1 < 49)
                store_sp(smc, F_AH, r1 * 272 + col * 2,
                         oc[nt][2] * inv1, oc[nt][3] * inv1);
        }
    }

    CP_WAIT0();
    __syncthreads();                 // Wout in + attn-out visible

    // ================= Phase 3: out-proj (3-pass split) =================
    {
        const uint32_t Bslot = sb + F_B + (wn >> 1) * 36864;
        float acc[4][4];
#pragma unroll
        for (int j = 0; j < 4; j++)
#pragma unroll
            for (int e = 0; e < 4; e++) acc[j][e] = 0.f;

#pragma unroll
        for (int kt = 0; kt < 8; kt++) {
            uint32_t ah[4], al[4], bh[2][4], bl[2][4];
            uint32_t aoff = (uint32_t)((wm * 16 + lrow) * 272
                                       + kt * 32 + lhalf * 16);
            LDM4(ah, sb + F_AH + aoff);
            LDM4(al, sb + F_AL + aoff);
#pragma unroll
            for (int nt = 0; nt < 2; nt++) {
                uint32_t boff = (uint32_t)((kt * 16 + lrow) * 144
                                           + ncl2 + nt * 32 + lhalf * 16);
                LDM4T(bh[nt], Bslot + boff);
                LDM4T(bl[nt], Bslot + 18432 + boff);
            }
#pragma unroll
            for (int j = 0; j < 4; j++)
                MMA_BF16(acc[j], ah, bh[j >> 1][2 * (j & 1)],
                         bh[j >> 1][2 * (j & 1) + 1]);
#pragma unroll
            for (int j = 0; j < 4; j++)
                MMA_BF16(acc[j], ah, bl[j >> 1][2 * (j & 1)],
                         bl[j >> 1][2 * (j & 1) + 1]);
#pragma unroll
            for (int j = 0; j < 4; j++)
                MMA_BF16(acc[j], al, bh[j >> 1][2 * (j & 1)],
                         bh[j >> 1][2 * (j & 1) + 1]);
        }

        const int r0 = wm * 16 + qrow, r1 = r0 + 8;
#pragma unroll
        for (int j = 0; j < 4; j++) {
            int col = wn * 32 + j * 8 + qt2;
            if (r0 < 49)
                *(float2*)(out + (win * WN + r0) * (size_t)D + col) =
                    make_float2(acc[j][0], acc[j][1]);
            if (r1 < 49)
                *(float2*)(out + (win * WN + r1) * (size_t)D + col) =
                    make_float2(acc[j][2], acc[j][3]);
        }
    }
}

// ============================== launcher ==============================
extern "C" void kernel_launch(void* const* d_in, const int* in_sizes, int n_in,
                              void* d_out, int out_size) {
    const float* x    = (const float*)d_in[0];
    const float* wqkv = (const float*)d_in[1];
    const float* wout = (const float*)d_in[2];
    const float* btab = (const float*)d_in[3];
    float* out = (float*)d_out;

    const int n_win = in_sizes[0] / (WN * D);

    cudaFuncSetAttribute(fused_win,
                         cudaFuncAttributeMaxDynamicSharedMemorySize, F_TOTAL);

    prepack_w<<<256, 256>>>(wqkv, wout);
    fused_win<<<n_win, 512, F_TOTAL>>>(x, btab, out);
}

// round 13
// speedup vs baseline: 1.3341x; 1.0913x over previous
#include <cuda_runtime.h>
#include <cstdint>

// ============================ helpers ============================
__device__ __forceinline__ uint32_t smem_u32(const void* p) {
    uint32_t a;
    asm("{ .reg .u64 t; cvta.to.shared.u64 t, %1; cvt.u32.u64 %0, t; }" : "=r"(a) : "l"(p));
    return a;
}
__device__ __forceinline__ unsigned short f2bf(float f) {
    unsigned short r; asm("cvt.rn.bf16.f32 %0, %1;" : "=h"(r) : "f"(f)); return r;
}
__device__ __forceinline__ float bf2f(unsigned short u) {
    return __uint_as_float(((uint32_t)u) << 16);
}
__device__ __forceinline__ uint32_t packbf(float a, float b) {
    uint32_t r; asm("cvt.rn.bf16x2.f32 %0, %1, %2;" : "=r"(r) : "f"(b), "f"(a)); return r;
}

#define LDM4(r, addr) \
    asm volatile("ldmatrix.sync.aligned.m8n8.x4.shared.b16 {%0,%1,%2,%3}, [%4];" \
        : "=r"((r)[0]), "=r"((r)[1]), "=r"((r)[2]), "=r"((r)[3]) : "r"(addr))

#define LDM4T(r, addr) \
    asm volatile("ldmatrix.sync.aligned.m8n8.x4.trans.shared.b16 {%0,%1,%2,%3}, [%4];" \
        : "=r"((r)[0]), "=r"((r)[1]), "=r"((r)[2]), "=r"((r)[3]) : "r"(addr))

#define MMA_BF16(c, a, b0, b1) \
    asm volatile("mma.sync.aligned.m16n8k16.row.col.f32.bf16.bf16.f32 " \
        "{%0,%1,%2,%3}, {%4,%5,%6,%7}, {%8,%9}, {%0,%1,%2,%3};" \
        : "+f"((c)[0]), "+f"((c)[1]), "+f"((c)[2]), "+f"((c)[3]) \
        : "r"((a)[0]), "r"((a)[1]), "r"((a)[2]), "r"((a)[3]), "r"(b0), "r"(b1))

#define CP_COMMIT() asm volatile("cp.async.commit_group;" ::: "memory")
#define CP_WAIT0()  asm volatile("cp.async.wait_group 0;" ::: "memory")
#define CP_WAIT1()  asm volatile("cp.async.wait_group 1;" ::: "memory")
__device__ __forceinline__ void cp16(uint32_t dst_smem, const void* src) {
    asm volatile("cp.async.cg.shared.global [%0], [%1], 16;"
        :: "r"(dst_smem), "l"(__cvta_generic_to_global(src)) : "memory");
}

// ============================ constants ============================
constexpr int WN  = 49;
constexpr int D   = 128;
constexpr float SCALE = 0.17677669529663687f;

// prepacked weights: 8 chunks (6 qkv + 2 wout), each [hi 18432 | lo 18432]
// per half: k(0..127)*144 + n_local(0..63)*2
__device__ unsigned char g_wpk[8][36864];

// smem layout: 2 window sets + slab ring + bias
// per window set (87040 B): XH(x-hi / attn-out-hi) 17408 | XL(x-lo -> Q) 17408 |
//                           KB(k -> attn-out-lo) 17408 | VH 17408 | VL 17408
constexpr int WSZ    = 87040;
constexpr int F_W    = 174080;   // 3 slab slots x 9216
constexpr int F_BIAS = 201728;   // 676 floats
constexpr int F_TOTAL = 204432;

// ======================= weight prepack kernel =======================
__global__ void prepack_w(const float* __restrict__ wqkv,
                          const float* __restrict__ wout)
{
    int idx = blockIdx.x * 256 + threadIdx.x;
    if (idx < 128 * 384) {
        int k = idx / 384, n = idx - (idx / 384) * 384;
        float v = wqkv[idx];
        unsigned short h = f2bf(v), l = f2bf(v - bf2f(h));
        int c = n >> 6, nn = n & 63;
        *(unsigned short*)(g_wpk[c] + k * 144 + nn * 2) = h;
        *(unsigned short*)(g_wpk[c] + 18432 + k * 144 + nn * 2) = l;
    } else if (idx < 128 * 384 + 128 * 128) {
        int i2 = idx - 128 * 384;
        int k = i2 >> 7, n = i2 & 127;
        float v = wout[i2];
        unsigned short h = f2bf(v), l = f2bf(v - bf2f(h));
        int c = 6 + (n >> 6), nn = n & 63;
        *(unsigned short*)(g_wpk[c] + k * 144 + nn * 2) = h;
        *(unsigned short*)(g_wpk[c] + 18432 + k * 144 + nn * 2) = l;
    }
}

// ============ slab issuers (one 16-k-row slab per kt) ============
// v / out slabs: 4 pieces (chunk-hi, chunk-lo) x 2 chunks = 9216 B
__device__ __forceinline__ void issue_v(uint32_t sb, int slot, int kt, int t) {
    if (t < 576) {
        int b = t / 144, i = t - b * 144;
        cp16(sb + F_W + slot * 9216 + b * 2304 + i * 16,
             g_wpk[4 + (b >> 1)] + (b & 1) * 18432 + kt * 2304 + i * 16);
    }
    CP_COMMIT();
}
__device__ __forceinline__ void issue_o(uint32_t sb, int slot, int kt, int t) {
    if (t < 576) {
        int b = t / 144, i = t - b * 144;
        cp16(sb + F_W + slot * 9216 + b * 2304 + i * 16,
             g_wpk[6 + (b >> 1)] + (b & 1) * 18432 + kt * 2304 + i * 16);
    }
    CP_COMMIT();
}
// q / k slabs: 2 pieces (2 chunks, hi only) = 4608 B
__device__ __forceinline__ void issue_q(uint32_t sb, int slot, int kt, int t) {
    if (t < 288) {
        int b = t / 144, i = t - b * 144;
        cp16(sb + F_W + slot * 9216 + b * 2304 + i * 16,
             g_wpk[b] + kt * 2304 + i * 16);
    }
    CP_COMMIT();
}
__device__ __forceinline__ void issue_k(uint32_t sb, int slot, int kt, int t) {
    if (t < 288) {
        int b = t / 144, i = t - b * 144;
        cp16(sb + F_W + slot * 9216 + b * 2304 + i * 16,
             g_wpk[2 + b] + kt * 2304 + i * 16);
    }
    CP_COMMIT();
}

// ================== fused kernel: 2 windows per CTA ==================
__global__ __launch_bounds__(1024, 1)
void fused2(const float* __restrict__ x, const float* __restrict__ btab,
            float* __restrict__ out, int n_win)
{
    extern __shared__ char smc[];
    const uint32_t sb = smem_u32(smc);
    const int t = threadIdx.x;
    const int w = t >> 5, lane = t & 31;
    const int wg = w >> 4, wl = w & 15;
    const int wm = wl & 3, wn = wl >> 2;
    const int lrow = lane & 15, lhalf = lane >> 4;
    const int qrow = lane >> 2, qt2 = (lane & 3) << 1;
    const size_t win = (size_t)blockIdx.x * 2 + wg;
    const bool valid = win < (size_t)n_win;
    const int B0 = wg * WSZ;
    float* bias_s = (float*)(smc + F_BIAS);

    // bootstrap v-slab ring (global slabs 0,1 -> slots 0,1)
    issue_v(sb, 0, 0, t);
    issue_v(sb, 1, 1, t);

    // zero both window data regions (pads MUST be 0)
    {
        uint4 z4 = make_uint4(0u, 0u, 0u, 0u);
        for (int i = t; i < 10880; i += 1024) ((uint4*)smc)[i] = z4;
    }
    if (t < 676) bias_s[t] = btab[t];

    // stage x -> split bf16 (XH/XL); invalid window stays zero
    {
        const float* xw = x + win * (size_t)(WN * D);
        for (int idx4 = (t & 511); idx4 < 1568; idx4 += 512) {
            int r  = idx4 >> 5;
            int c4 = (idx4 & 31) << 2;
            float4 v = valid ? *(const float4*)(xw + r * D + c4)
                             : make_float4(0.f, 0.f, 0.f, 0.f);
            float vv[4] = {v.x, v.y, v.z, v.w};
            unsigned short hh[4], ll[4];
#pragma unroll
            for (int e = 0; e < 4; e++) {
                hh[e] = f2bf(vv[e]); ll[e] = f2bf(vv[e] - bf2f(hh[e]));
            }
            int off = B0 + r * 272 + c4 * 2;
            *(uint2*)(smc + off) = make_uint2(
                (uint32_t)hh[0] | ((uint32_t)hh[1] << 16),
                (uint32_t)hh[2] | ((uint32_t)hh[3] << 16));
            *(uint2*)(smc + 17408 + off) = make_uint2(
                (uint32_t)ll[0] | ((uint32_t)ll[1] << 16),
                (uint32_t)ll[2] | ((uint32_t)ll[3] << 16));
        }
    }

    // ================= stage V (3-pass split), slabs 0..7 =================
    {
        float acc[4][4];
#pragma unroll
        for (int j = 0; j < 4; j++)
#pragma unroll
            for (int e = 0; e < 4; e++) acc[j][e] = 0.f;

#pragma unroll 1
        for (int kt = 0; kt < 8; kt++) {
            if (kt < 7) CP_WAIT1(); else CP_WAIT0();
            __syncthreads();
            if (kt < 6) issue_v(sb, (kt + 2) % 3, kt + 2, t);
            const int slot = kt % 3;

            uint32_t ah[4], al[4], bh[2][4], bl[2][4];
            uint32_t aoff = (uint32_t)(B0 + (wm * 16 + lrow) * 272
                                       + kt * 32 + lhalf * 16);
            LDM4(ah, sb + aoff);
            LDM4(al, sb + 17408 + aoff);
            uint32_t pbase = sb + F_W + slot * 9216 + (wn >> 1) * 4608;
#pragma unroll
            for (int nt = 0; nt < 2; nt++) {
                uint32_t boff = (uint32_t)(lrow * 144
                                + ((wn & 1) * 32 + nt * 16) * 2 + lhalf * 16);
                LDM4T(bh[nt], pbase + boff);
                LDM4T(bl[nt], pbase + 2304 + boff);
            }
#pragma unroll
            for (int j = 0; j < 4; j++)
                MMA_BF16(acc[j], ah, bh[j >> 1][2 * (j & 1)],
                         bh[j >> 1][2 * (j & 1) + 1]);
#pragma unroll
            for (int j = 0; j < 4; j++)
                MMA_BF16(acc[j], ah, bl[j >> 1][2 * (j & 1)],
                         bl[j >> 1][2 * (j & 1) + 1]);
#pragma unroll
            for (int j = 0; j < 4; j++)
                MMA_BF16(acc[j], al, bh[j >> 1][2 * (j & 1)],
                         bh[j >> 1][2 * (j & 1) + 1]);
        }
        // pre-issue q slabs (global 8,9 -> slots 2,0)
        issue_q(sb, 2, 0, t);
        issue_q(sb, 0, 1, t);

        // epilogue: split v -> VH/VL
        const int r0 = wm * 16 + qrow, r1 = r0 + 8;
#pragma unroll
        for (int j = 0; j < 4; j++) {
            int cb = (wn * 32 + j * 8 + qt2) * 2;
            {
                int off = r0 * 272 + cb;
                uint32_t hp = packbf(acc[j][0], acc[j][1]);
                float ra = acc[j][0] - __uint_as_float(hp << 16);
                float rb = acc[j][1] - __uint_as_float(hp & 0xFFFF0000u);
                *(uint32_t*)(smc + B0 + 52224 + off) = hp;
                *(uint32_t*)(smc + B0 + 69632 + off) = packbf(ra, rb);
            }
            {
                int off = r1 * 272 + cb;
                uint32_t hp = packbf(acc[j][2], acc[j][3]);
                float ra = acc[j][2] - __uint_as_float(hp << 16);
                float rb = acc[j][3] - __uint_as_float(hp & 0xFFFF0000u);
                *(uint32_t*)(smc + B0 + 52224 + off) = hp;
                *(uint32_t*)(smc + B0 + 69632 + off) = packbf(ra, rb);
            }
        }
    }

    // ============ stages Q (ss=0, slabs 8..15) and K (ss=1, 16..23) ============
#pragma unroll 1
    for (int ss = 0; ss < 2; ss++) {
        float acc[4][4];
#pragma unroll
        for (int j = 0; j < 4; j++)
#pragma unroll
            for (int e = 0; e < 4; e++) acc[j][e] = 0.f;

#pragma unroll 1
        for (int kt = 0; kt < 8; kt++) {
            if (kt < 7) CP_WAIT1(); else CP_WAIT0();
            __syncthreads();
            if (kt < 6) {
                if (ss == 0) issue_q(sb, (kt + 10) % 3, kt + 2, t);
                else         issue_k(sb, kt % 3,        kt + 2, t);
            }
            const int slot = (ss == 0) ? (2 + kt) % 3 : (1 + kt) % 3;

            uint32_t ah[4], bh[2][4];
            uint32_t aoff = (uint32_t)(B0 + (wm * 16 + lrow) * 272
                                       + kt * 32 + lhalf * 16);
            LDM4(ah, sb + aoff);
            uint32_t pbase = sb + F_W + slot * 9216 + (wn >> 1) * 2304;
#pragma unroll
            for (int nt = 0; nt < 2; nt++) {
                uint32_t boff = (uint32_t)(lrow * 144
                                + ((wn & 1) * 32 + nt * 16) * 2 + lhalf * 16);
                LDM4T(bh[nt], pbase + boff);
            }
#pragma unroll
            for (int j = 0; j < 4; j++)
                MMA_BF16(acc[j], ah, bh[j >> 1][2 * (j & 1)],
                         bh[j >> 1][2 * (j & 1) + 1]);
        }
        if (ss == 0) {       // pre-issue k slabs (16,17 -> slots 1,2)
            issue_k(sb, 1, 0, t);
            issue_k(sb, 2, 1, t);
        } else {             // pre-issue out slabs (24,25 -> slots 0,1)
            issue_o(sb, 0, 0, t);
            issue_o(sb, 1, 1, t);
        }
        // epilogue: q -> XL (B0+17408), k -> KB (B0+34816), single bf16
        const int base = B0 + ((ss == 0) ? 17408 : 34816);
        const int r0 = wm * 16 + qrow, r1 = r0 + 8;
#pragma unroll
        for (int j = 0; j < 4; j++) {
            int cb = (wn * 32 + j * 8 + qt2) * 2;
            *(uint32_t*)(smc + base + r0 * 272 + cb) = packbf(acc[j][0], acc[j][1]);
            *(uint32_t*)(smc + base + r1 * 272 + cb) = packbf(acc[j][2], acc[j][3]);
        }
    }
    __syncthreads();                 // Q/K/V visible for attention

    // ================= attention: 1 task per warp (wl) =================
    {
        const int h  = wl >> 2;
        const int i0 = (wl & 3) << 4;
        const uint32_t QB = sb + B0 + 17408;
        const uint32_t KBa = sb + B0 + 34816;
        const uint32_t VB = sb + B0 + 52224;

        float sc[7][4];
#pragma unroll
        for (int nt = 0; nt < 7; nt++)
#pragma unroll
            for (int e = 0; e < 4; e++) sc[nt][e] = 0.f;

        // S = q k^T, single-pass
#pragma unroll
        for (int kt = 0; kt < 2; kt++) {
            uint32_t ah[4], bh[4][4];
            uint32_t coff = (uint32_t)((h * 32 + kt * 16) * 2 + lhalf * 16);
            LDM4(ah, QB + (uint32_t)((i0 + lrow) * 272) + coff);
#pragma unroll
            for (int g = 0; g < 4; g++)
                LDM4(bh[g], KBa + (uint32_t)((g * 16 + lrow) * 272) + coff);
#pragma unroll
            for (int nt = 0; nt < 7; nt++)
                MMA_BF16(sc[nt], ah, bh[nt >> 1][nt & 1], bh[nt >> 1][2 + (nt & 1)]);
        }

        // softmax in fragments (unnormalized)
        const int r0 = i0 + qrow, r1 = r0 + 8;
        const int gi0 = r0 / 7, gj0 = r0 - 7 * gi0;
        const int gi1 = r1 / 7, gj1 = r1 - 7 * gi1;
        float rs0 = 0.f, rs1 = 0.f;
#pragma unroll
        for (int nt = 0; nt < 7; nt++) {
#pragma unroll
            for (int e = 0; e < 4; e++) {
                int j = nt * 8 + qt2 + (e & 1);
                int r = (e < 2) ? r0 : r1;
                float ev = 0.f;
                if (r < 49 && j < 49) {
                    int gj2 = j / 7;
                    int gjj = j - 7 * gj2;
                    int gi = (e < 2) ? gi0 : gi1;
                    int gj = (e < 2) ? gj0 : gj1;
                    int bidx = ((gi - gj2 + 6) * 13 + (gj - gjj + 6)) * 4 + h;
                    ev = __expf(sc[nt][e] * SCALE + bias_s[bidx]);
                }
                sc[nt][e] = ev;
                if (e < 2) rs0 += ev; else rs1 += ev;
            }
        }
        rs0 += __shfl_xor_sync(0xFFFFFFFFu, rs0, 1);
        rs0 += __shfl_xor_sync(0xFFFFFFFFu, rs0, 2);
        rs1 += __shfl_xor_sync(0xFFFFFFFFu, rs1, 1);
        rs1 += __shfl_xor_sync(0xFFFFFFFFu, rs1, 2);
        const float inv0 = (r0 < 49) ? 1.f / rs0 : 0.f;
        const float inv1 = (r1 < 49) ? 1.f / rs1 : 0.f;

        // O = P V (split P in-register x split V)
        float oc[4][4];
#pragma unroll
        for (int nt = 0; nt < 4; nt++)
#pragma unroll
            for (int e = 0; e < 4; e++) oc[nt][e] = 0.f;

#pragma unroll
        for (int kt2 = 0; kt2 < 4; kt2++) {
            const int lo = 2 * kt2, hi = lo + 1;
            float pe[8];
            pe[0] = sc[lo][0]; pe[1] = sc[lo][1];
            pe[2] = sc[lo][2]; pe[3] = sc[lo][3];
            if (hi < 7) {
                pe[4] = sc[hi][0]; pe[5] = sc[hi][1];
                pe[6] = sc[hi][2]; pe[7] = sc[hi][3];
            } else {
                pe[4] = pe[5] = pe[6] = pe[7] = 0.f;
            }
            uint32_t ph[4], pl[4];
#pragma unroll
            for (int g = 0; g < 4; g++) {
                float a = pe[2 * g], b = pe[2 * g + 1];
                uint32_t hp = packbf(a, b);
                float ra = a - __uint_as_float(hp << 16);
                float rb = b - __uint_as_float(hp & 0xFFFF0000u);
                ph[g] = hp;
                pl[g] = packbf(ra, rb);
            }
            uint32_t vh[2][4], vl[2][4];
#pragma unroll
            for (int g = 0; g < 2; g++) {
                uint32_t voff = (uint32_t)((kt2 * 16 + lrow) * 272
                                           + h * 64 + g * 32 + lhalf * 16);
                LDM4T(vh[g], VB + voff);
                LDM4T(vl[g], VB + 17408 + voff);
            }
#pragma unroll
            for (int nt = 0; nt < 4; nt++)
                MMA_BF16(oc[nt], ph, vh[nt >> 1][2 * (nt & 1)],
                         vh[nt >> 1][2 * (nt & 1) + 1]);
#pragma unroll
            for (int nt = 0; nt < 4; nt++)
                MMA_BF16(oc[nt], ph, vl[nt >> 1][2 * (nt & 1)],
                         vl[nt >> 1][2 * (nt & 1) + 1]);
#pragma unroll
            for (int nt = 0; nt < 4; nt++)
                MMA_BF16(oc[nt], pl, vh[nt >> 1][2 * (nt & 1)],
                         vh[nt >> 1][2 * (nt & 1) + 1]);
        }

        __syncthreads();   // all Q/K reads done before attn-out overwrites

        // attn-out: hi -> XH (B0), lo -> KB (B0+34816), split bf16
#pragma unroll
        for (int nt = 0; nt < 4; nt++) {
            int cb = (h * 32 + nt * 8 + qt2) * 2;
            if (r0 < 49) {
                float a = oc[nt][0] * inv0, b = oc[nt][1] * inv0;
                uint32_t hp = packbf(a, b);
                float ra = a - __uint_as_float(hp << 16);
                float rb = b - __uint_as_float(hp & 0xFFFF0000u);
                int off = r0 * 272 + cb;
                *(uint32_t*)(smc + B0 + off) = hp;
                *(uint32_t*)(smc + B0 + 34816 + off) = packbf(ra, rb);
            }
            if (r1 < 49) {
                float a = oc[nt][2] * inv1, b = oc[nt][3] * inv1;
                uint32_t hp = packbf(a, b);
                float ra = a - __uint_as_float(hp << 16);
                float rb = b - __uint_as_float(hp & 0xFFFF0000u);
                int off = r1 * 272 + cb;
                *(uint32_t*)(smc + B0 + off) = hp;
                *(uint32_t*)(smc + B0 + 34816 + off) = packbf(ra, rb);
            }
        }
    }

    // ================= out-proj (3-pass split), slabs 24..31 =================
    {
        float acc[4][4];
#pragma unroll
        for (int j = 0; j < 4; j++)
#pragma unroll
            for (int e = 0; e < 4; e++) acc[j][e] = 0.f;

#pragma unroll 1
        for (int kt = 0; kt < 8; kt++) {
            if (kt < 7) CP_WAIT1(); else CP_WAIT0();
            __syncthreads();
            if (kt < 6) issue_o(sb, (kt + 2) % 3, kt + 2, t);
            const int slot = kt % 3;

            uint32_t ah[4], al[4], bh[2][4], bl[2][4];
            uint32_t aoff = (uint32_t)(B0 + (wm * 16 + lrow) * 272
                                       + kt * 32 + lhalf * 16);
            LDM4(ah, sb + aoff);                 // attn-out hi (XH)
            LDM4(al, sb + 34816 + aoff);         // attn-out lo (KB)
            uint32_t pbase = sb + F_W + slot * 9216 + (wn >> 1) * 4608;
#pragma unroll
            for (int nt = 0; nt < 2; nt++) {
                uint32_t boff = (uint32_t)(lrow * 144
                                + ((wn & 1) * 32 + nt * 16) * 2 + lhalf * 16);
                LDM4T(bh[nt], pbase + boff);
                LDM4T(bl[nt], pbase + 2304 + boff);
            }
#pragma unroll
            for (int j = 0; j < 4; j++)
                MMA_BF16(acc[j], ah, bh[j >> 1][2 * (j & 1)],
                         bh[j >> 1][2 * (j & 1) + 1]);
#pragma unroll
            for (int j = 0; j < 4; j++)
                MMA_BF16(acc[j], ah, bl[j >> 1][2 * (j & 1)],
                         bl[j >> 1][2 * (j & 1) + 1]);
#pragma unroll
            for (int j = 0; j < 4; j++)
                MMA_BF16(acc[j], al, bh[j >> 1][2 * (j & 1)],
                         bh[j >> 1][2 * (j & 1) + 1]);
        }

        const int r0 = wm * 16 + qrow, r1 = r0 + 8;
#pragma unroll
        for (int j = 0; j < 4; j++) {
            int col = wn * 32 + j * 8 + qt2;
            if (valid && r0 < 49)
                *(float2*)(out + (win * WN + r0) * (size_t)D + col) =
                    make_float2(acc[j][0], acc[j][1]);
            if (valid && r1 < 49)
                *(float2*)(out + (win * WN + r1) * (size_t)D + col) =
                    make_float2(acc[j][2], acc[j][3]);
        }
    }
}

// ============================== launcher ==============================
extern "C" void kernel_launch(void* const* d_in, const int* in_sizes, int n_in,
                              void* d_out, int out_size) {
    const float* x    = (const float*)d_in[0];
    const float* wqkv = (const float*)d_in[1];
    const float* wout = (const float*)d_in[2];
    const float* btab = (const float*)d_in[3];
    float* out = (float*)d_out;

    const int n_win = in_sizes[0] / (WN * D);
    const int grid = (n_win + 1) / 2;

    cudaFuncSetAttribute(fused2,
                         cudaFuncAttributeMaxDynamicSharedMemorySize, F_TOTAL);

    prepack_w<<<256, 256>>>(wqkv, wout);
    fused2<<<grid, 1024, F_TOTAL>>>(x, btab, out, n_win);
}

// round 14
// speedup vs baseline: 1.4447x; 1.0829x over previous
#include <cuda_runtime.h>
#include <cstdint>

// ============================ helpers ============================
__device__ __forceinline__ uint32_t smem_u32(const void* p) {
    uint32_t a;
    asm("{ .reg .u64 t; cvta.to.shared.u64 t, %1; cvt.u32.u64 %0, t; }" : "=r"(a) : "l"(p));
    return a;
}
__device__ __forceinline__ unsigned short f2bf(float f) {
    unsigned short r; asm("cvt.rn.bf16.f32 %0, %1;" : "=h"(r) : "f"(f)); return r;
}
__device__ __forceinline__ float bf2f(unsigned short u) {
    return __uint_as_float(((uint32_t)u) << 16);
}
__device__ __forceinline__ uint32_t packbf(float a, float b) {
    uint32_t r; asm("cvt.rn.bf16x2.f32 %0, %1, %2;" : "=r"(r) : "f"(b), "f"(a)); return r;
}

#define LDM4(r, addr) \
    asm volatile("ldmatrix.sync.aligned.m8n8.x4.shared.b16 {%0,%1,%2,%3}, [%4];" \
        : "=r"((r)[0]), "=r"((r)[1]), "=r"((r)[2]), "=r"((r)[3]) : "r"(addr))

#define LDM4T(r, addr) \
    asm volatile("ldmatrix.sync.aligned.m8n8.x4.trans.shared.b16 {%0,%1,%2,%3}, [%4];" \
        : "=r"((r)[0]), "=r"((r)[1]), "=r"((r)[2]), "=r"((r)[3]) : "r"(addr))

#define MMA_BF16(c, a, b0, b1) \
    asm volatile("mma.sync.aligned.m16n8k16.row.col.f32.bf16.bf16.f32 " \
        "{%0,%1,%2,%3}, {%4,%5,%6,%7}, {%8,%9}, {%0,%1,%2,%3};" \
        : "+f"((c)[0]), "+f"((c)[1]), "+f"((c)[2]), "+f"((c)[3]) \
        : "r"((a)[0]), "r"((a)[1]), "r"((a)[2]), "r"((a)[3]), "r"(b0), "r"(b1))

#define CP_COMMIT() asm volatile("cp.async.commit_group;" ::: "memory")
#define CP_WAIT0()  asm volatile("cp.async.wait_group 0;" ::: "memory")
#define CP_WAIT1()  asm volatile("cp.async.wait_group 1;" ::: "memory")
#define CP_WAIT2()  asm volatile("cp.async.wait_group 2;" ::: "memory")
__device__ __forceinline__ void cp16(uint32_t dst_smem, const void* src) {
    asm volatile("cp.async.cg.shared.global [%0], [%1], 16;"
        :: "r"(dst_smem), "l"(__cvta_generic_to_global(src)) : "memory");
}

// ============================ constants ============================
constexpr int WN  = 49;
constexpr int D   = 128;
constexpr float SCALE = 0.17677669529663687f;

// prepacked weights: 8 chunks (6 qkv + 2 wout), each [hi 18432 | lo 18432]
// per half: k(0..127)*144 + n_local(0..63)*2
__device__ unsigned char g_wpk[8][36864];

// per-CTA smem (one window):
// XH(x-hi/attn-hi) 0 | XL(x-lo->Q) 17408 | KB(k->attn-lo) 34816 |
// VH 52224 | VL 69632 | W ring 87040 (18432) | bias 105472
constexpr int S_XL   = 17408;
constexpr int S_KB   = 34816;
constexpr int S_VH   = 52224;
constexpr int S_VL   = 69632;
constexpr int F_W    = 87040;
constexpr int F_BIAS = 105472;
constexpr int F_TOTAL = 108176;

// ======================= weight prepack kernel =======================
__global__ void prepack_w(const float* __restrict__ wqkv,
                          const float* __restrict__ wout)
{
    int idx = blockIdx.x * 256 + threadIdx.x;
    if (idx < 128 * 384) {
        int k = idx / 384, n = idx - (idx / 384) * 384;
        float v = wqkv[idx];
        unsigned short h = f2bf(v), l = f2bf(v - bf2f(h));
        int c = n >> 6, nn = n & 63;
        *(unsigned short*)(g_wpk[c] + k * 144 + nn * 2) = h;
        *(unsigned short*)(g_wpk[c] + 18432 + k * 144 + nn * 2) = l;
    } else if (idx < 128 * 384 + 128 * 128) {
        int i2 = idx - 128 * 384;
        int k = i2 >> 7, n = i2 & 127;
        float v = wout[i2];
        unsigned short h = f2bf(v), l = f2bf(v - bf2f(h));
        int c = 6 + (n >> 6), nn = n & 63;
        *(unsigned short*)(g_wpk[c] + k * 144 + nn * 2) = h;
        *(unsigned short*)(g_wpk[c] + 18432 + k * 144 + nn * 2) = l;
    }
}

// ============ slab issuers ============
// v / out slabs: 9216 B (2 chunks x hi/lo, one kt); ring2 slots {0,9216}
__device__ __forceinline__ void issue_vo(uint32_t sb, int slot, int kt, int t,
                                         int cbase) {
    for (int i = t; i < 576; i += 512) {
        int b = i / 144, ii = i - b * 144;
        cp16(sb + F_W + slot * 9216 + b * 2304 + ii * 16,
             g_wpk[cbase + (b >> 1)] + (b & 1) * 18432 + kt * 2304 + ii * 16);
    }
    CP_COMMIT();
}
// q / k slabs: 4608 B (2 chunks, hi only); ring4 slots {0,4608,9216,13824}
__device__ __forceinline__ void issue_qk(uint32_t sb, int slot, int kt, int t,
                                         int cbase) {
    if (t < 288) {
        int b = t / 144, ii = t - b * 144;
        cp16(sb + F_W + slot * 4608 + b * 2304 + ii * 16,
             g_wpk[cbase + b] + kt * 2304 + ii * 16);
    }
    CP_COMMIT();
}

// ================== fused kernel: 1 window / CTA, 2 CTAs / SM ==================
__global__ __launch_bounds__(512, 2)
void fused1(const float* __restrict__ x, const float* __restrict__ btab,
            float* __restrict__ out)
{
    extern __shared__ char smc[];
    const uint32_t sb = smem_u32(smc);
    const int t = threadIdx.x;
    const int w = t >> 5, lane = t & 31;
    const int wm = w & 3, wn = w >> 2;
    const int lrow = lane & 15, lhalf = lane >> 4;
    const int qrow = lane >> 2, qt2 = (lane & 3) << 1;
    const size_t win = blockIdx.x;
    float* bias_s = (float*)(smc + F_BIAS);

    // bootstrap v-slab ring
    issue_vo(sb, 0, 0, t, 4);
    issue_vo(sb, 1, 1, t, 4);

    // zero window data region (pads MUST be 0)
    {
        uint4 z4 = make_uint4(0u, 0u, 0u, 0u);
        for (int i = t; i < 5440; i += 512) ((uint4*)smc)[i] = z4;
    }
    for (int i = t; i < 676; i += 512) bias_s[i] = btab[i];

    // stage x -> split bf16 (XH/XL)
    {
        const float* xw = x + win * (size_t)(WN * D);
        for (int idx4 = t; idx4 < 1568; idx4 += 512) {
            int r  = idx4 >> 5;
            int c4 = (idx4 & 31) << 2;
            float4 v = *(const float4*)(xw + r * D + c4);
            float vv[4] = {v.x, v.y, v.z, v.w};
            unsigned short hh[4], ll[4];
#pragma unroll
            for (int e = 0; e < 4; e++) {
                hh[e] = f2bf(vv[e]); ll[e] = f2bf(vv[e] - bf2f(hh[e]));
            }
            int off = r * 272 + c4 * 2;
            *(uint2*)(smc + off) = make_uint2(
                (uint32_t)hh[0] | ((uint32_t)hh[1] << 16),
                (uint32_t)hh[2] | ((uint32_t)hh[3] << 16));
            *(uint2*)(smc + S_XL + off) = make_uint2(
                (uint32_t)ll[0] | ((uint32_t)ll[1] << 16),
                (uint32_t)ll[2] | ((uint32_t)ll[3] << 16));
        }
    }

    // ================= stage V (3-pass split), ring2 =================
    {
        float acc[4][4];
#pragma unroll
        for (int j = 0; j < 4; j++)
#pragma unroll
            for (int e = 0; e < 4; e++) acc[j][e] = 0.f;

#pragma unroll 1
        for (int kt = 0; kt < 8; kt++) {
            if (kt < 7) CP_WAIT1(); else CP_WAIT0();
            __syncthreads();                       // slab kt ready

            uint32_t ah[4], al[4], bh[2][4], bl[2][4];
            uint32_t aoff = (uint32_t)((wm * 16 + lrow) * 272
                                       + kt * 32 + lhalf * 16);
            LDM4(ah, sb + aoff);
            LDM4(al, sb + S_XL + aoff);
            uint32_t pbase = sb + F_W + (kt & 1) * 9216 + (wn >> 1) * 4608;
#pragma unroll
            for (int nt = 0; nt < 2; nt++) {
                uint32_t boff = (uint32_t)(lrow * 144
                                + ((wn & 1) * 32 + nt * 16) * 2 + lhalf * 16);
                LDM4T(bh[nt], pbase + boff);
                LDM4T(bl[nt], pbase + 2304 + boff);
            }
#pragma unroll
            for (int j = 0; j < 4; j++)
                MMA_BF16(acc[j], ah, bh[j >> 1][2 * (j & 1)],
                         bh[j >> 1][2 * (j & 1) + 1]);
#pragma unroll
            for (int j = 0; j < 4; j++)
                MMA_BF16(acc[j], ah, bl[j >> 1][2 * (j & 1)],
                         bl[j >> 1][2 * (j & 1) + 1]);
#pragma unroll
            for (int j = 0; j < 4; j++)
                MMA_BF16(acc[j], al, bh[j >> 1][2 * (j & 1)],
                         bh[j >> 1][2 * (j & 1) + 1]);

            __syncthreads();                       // slot drained
            if (kt < 6) issue_vo(sb, kt & 1, kt + 2, t, 4);
        }
        // pre-issue q slabs (ring4 slots 0,1,2)
        issue_qk(sb, 0, 0, t, 0);
        issue_qk(sb, 1, 1, t, 0);
        issue_qk(sb, 2, 2, t, 0);

        // epilogue: split v -> VH/VL
        const int r0 = wm * 16 + qrow, r1 = r0 + 8;
#pragma unroll
        for (int j = 0; j < 4; j++) {
            int cb = (wn * 32 + j * 8 + qt2) * 2;
            {
                int off = r0 * 272 + cb;
                uint32_t hp = packbf(acc[j][0], acc[j][1]);
                float ra = acc[j][0] - __uint_as_float(hp << 16);
                float rb = acc[j][1] - __uint_as_float(hp & 0xFFFF0000u);
                *(uint32_t*)(smc + S_VH + off) = hp;
                *(uint32_t*)(smc + S_VL + off) = packbf(ra, rb);
            }
            {
                int off = r1 * 272 + cb;
                uint32_t hp = packbf(acc[j][2], acc[j][3]);
                float ra = acc[j][2] - __uint_as_float(hp << 16);
                float rb = acc[j][3] - __uint_as_float(hp & 0xFFFF0000u);
                *(uint32_t*)(smc + S_VH + off) = hp;
                *(uint32_t*)(smc + S_VL + off) = packbf(ra, rb);
            }
        }
    }

    // ============ stages Q (ss=0) and K (ss=1): single-pass, ring4 ============
#pragma unroll 1
    for (int ss = 0; ss < 2; ss++) {
        float acc[4][4];
#pragma unroll
        for (int j = 0; j < 4; j++)
#pragma unroll
            for (int e = 0; e < 4; e++) acc[j][e] = 0.f;

#pragma unroll 1
        for (int kt = 0; kt < 8; kt++) {
            if (kt < 6) CP_WAIT2(); else if (kt == 6) CP_WAIT1(); else CP_WAIT0();
            __syncthreads();                       // slab kt ready; kt-1 drained
            if (kt < 5) issue_qk(sb, (kt + 3) & 3, kt + 3, t, ss == 0 ? 0 : 2);

            uint32_t ah[4], bh[2][4];
            uint32_t aoff = (uint32_t)((wm * 16 + lrow) * 272
                                       + kt * 32 + lhalf * 16);
            LDM4(ah, sb + aoff);                   // x-hi only
            uint32_t pbase = sb + F_W + (kt & 3) * 4608 + (wn >> 1) * 2304;
#pragma unroll
            for (int nt = 0; nt < 2; nt++) {
                uint32_t boff = (uint32_t)(lrow * 144
                                + ((wn & 1) * 32 + nt * 16) * 2 + lhalf * 16);
                LDM4T(bh[nt], pbase + boff);
            }
#pragma unroll
            for (int j = 0; j < 4; j++)
                MMA_BF16(acc[j], ah, bh[j >> 1][2 * (j & 1)],
                         bh[j >> 1][2 * (j & 1) + 1]);
        }
        if (ss == 0) {       // pre-issue k slabs: slots 0,1,2 (drained kt4,5,6)
            issue_qk(sb, 0, 0, t, 2);
            issue_qk(sb, 1, 1, t, 2);
            issue_qk(sb, 2, 2, t, 2);
        }
        // epilogue: q -> XL, k -> KB (single bf16)
        const int base = (ss == 0) ? S_XL : S_KB;
        const int r0 = wm * 16 + qrow, r1 = r0 + 8;
#pragma unroll
        for (int j = 0; j < 4; j++) {
            int cb = (wn * 32 + j * 8 + qt2) * 2;
            *(uint32_t*)(smc + base + r0 * 272 + cb) = packbf(acc[j][0], acc[j][1]);
            *(uint32_t*)(smc + base + r1 * 272 + cb) = packbf(acc[j][2], acc[j][3]);
        }
    }
    __syncthreads();                 // Q/K/V visible; K kt7 slot drained
    // pre-issue out-proj slabs (ring2)
    issue_vo(sb, 0, 0, t, 6);
    issue_vo(sb, 1, 1, t, 6);

    // ================= attention: 1 task per warp =================
    {
        const int h  = w >> 2;
        const int i0 = (w & 3) << 4;
        const uint32_t QB = sb + S_XL;
        const uint32_t KBa = sb + S_KB;
        const uint32_t VB = sb + S_VH;

        float sc[7][4];
#pragma unroll
        for (int nt = 0; nt < 7; nt++)
#pragma unroll
            for (int e = 0; e < 4; e++) sc[nt][e] = 0.f;

        // S = q k^T, single-pass
#pragma unroll
        for (int kt = 0; kt < 2; kt++) {
            uint32_t ah[4], bh[4][4];
            uint32_t coff = (uint32_t)((h * 32 + kt * 16) * 2 + lhalf * 16);
            LDM4(ah, QB + (uint32_t)((i0 + lrow) * 272) + coff);
#pragma unroll
            for (int g = 0; g < 4; g++)
                LDM4(bh[g], KBa + (uint32_t)((g * 16 + lrow) * 272) + coff);
#pragma unroll
            for (int nt = 0; nt < 7; nt++)
                MMA_BF16(sc[nt], ah, bh[nt >> 1][nt & 1], bh[nt >> 1][2 + (nt & 1)]);
        }

        // softmax in fragments (unnormalized)
        const int r0 = i0 + qrow, r1 = r0 + 8;
        const int gi0 = r0 / 7, gj0 = r0 - 7 * gi0;
        const int gi1 = r1 / 7, gj1 = r1 - 7 * gi1;
        float rs0 = 0.f, rs1 = 0.f;
#pragma unroll
        for (int nt = 0; nt < 7; nt++) {
#pragma unroll
            for (int e = 0; e < 4; e++) {
                int j = nt * 8 + qt2 + (e & 1);
                int r = (e < 2) ? r0 : r1;
                float ev = 0.f;
                if (r < 49 && j < 49) {
                    int gj2 = j / 7;
                    int gjj = j - 7 * gj2;
                    int gi = (e < 2) ? gi0 : gi1;
                    int gj = (e < 2) ? gj0 : gj1;
                    int bidx = ((gi - gj2 + 6) * 13 + (gj - gjj + 6)) * 4 + h;
                    ev = __expf(sc[nt][e] * SCALE + bias_s[bidx]);
                }
                sc[nt][e] = ev;
                if (e < 2) rs0 += ev; else rs1 += ev;
            }
        }
        rs0 += __shfl_xor_sync(0xFFFFFFFFu, rs0, 1);
        rs0 += __shfl_xor_sync(0xFFFFFFFFu, rs0, 2);
        rs1 += __shfl_xor_sync(0xFFFFFFFFu, rs1, 1);
        rs1 += __shfl_xor_sync(0xFFFFFFFFu, rs1, 2);
        const float inv0 = (r0 < 49) ? 1.f / rs0 : 0.f;
        const float inv1 = (r1 < 49) ? 1.f / rs1 : 0.f;

        // O = P V (split P in-register x split V)
        float oc[4][4];
#pragma unroll
        for (int nt = 0; nt < 4; nt++)
#pragma unroll
            for (int e = 0; e < 4; e++) oc[nt][e] = 0.f;

#pragma unroll
        for (int kt2 = 0; kt2 < 4; kt2++) {
            const int lo = 2 * kt2, hi = lo + 1;
            float pe[8];
            pe[0] = sc[lo][0]; pe[1] = sc[lo][1];
            pe[2] = sc[lo][2]; pe[3] = sc[lo][3];
            if (hi < 7) {
                pe[4] = sc[hi][0]; pe[5] = sc[hi][1];
                pe[6] = sc[hi][2]; pe[7] = sc[hi][3];
            } else {
                pe[4] = pe[5] = pe[6] = pe[7] = 0.f;
            }
            uint32_t ph[4], pl[4];
#pragma unroll
            for (int g = 0; g < 4; g++) {
                float a = pe[2 * g], b = pe[2 * g + 1];
                uint32_t hp = packbf(a, b);
                float ra = a - __uint_as_float(hp << 16);
                float rb = b - __uint_as_float(hp & 0xFFFF0000u);
                ph[g] = hp;
                pl[g] = packbf(ra, rb);
            }
            uint32_t vh[2][4], vl[2][4];
#pragma unroll
            for (int g = 0; g < 2; g++) {
                uint32_t voff = (uint32_t)((kt2 * 16 + lrow) * 272
                                           + h * 64 + g * 32 + lhalf * 16);
                LDM4T(vh[g], VB + voff);
                LDM4T(vl[g], VB + 17408 + voff);
            }
#pragma unroll
            for (int nt = 0; nt < 4; nt++)
                MMA_BF16(oc[nt], ph, vh[nt >> 1][2 * (nt & 1)],
                         vh[nt >> 1][2 * (nt & 1) + 1]);
#pragma unroll
            for (int nt = 0; nt < 4; nt++)
                MMA_BF16(oc[nt], ph, vl[nt >> 1][2 * (nt & 1)],
                         vl[nt >> 1][2 * (nt & 1) + 1]);
#pragma unroll
            for (int nt = 0; nt < 4; nt++)
                MMA_BF16(oc[nt], pl, vh[nt >> 1][2 * (nt & 1)],
                         vh[nt >> 1][2 * (nt & 1) + 1]);
        }

        __syncthreads();   // all Q/K reads done before attn-out overwrites

        // attn-out: hi -> XH, lo -> KB (split bf16)
#pragma unroll
        for (int nt = 0; nt < 4; nt++) {
            int cb = (h * 32 + nt * 8 + qt2) * 2;
            if (r0 < 49) {
                float a = oc[nt][0] * inv0, b = oc[nt][1] * inv0;
                uint32_t hp = packbf(a, b);
                float ra = a - __uint_as_float(hp << 16);
                float rb = b - __uint_as_float(hp & 0xFFFF0000u);
                int off = r0 * 272 + cb;
                *(uint32_t*)(smc + off) = hp;
                *(uint32_t*)(smc + S_KB + off) = packbf(ra, rb);
            }
            if (r1 < 49) {
                float a = oc[nt][2] * inv1, b = oc[nt][3] * inv1;
                uint32_t hp = packbf(a, b);
                float ra = a - __uint_as_float(hp << 16);
                float rb = b - __uint_as_float(hp & 0xFFFF0000u);
                int off = r1 * 272 + cb;
                *(uint32_t*)(smc + off) = hp;
                *(uint32_t*)(smc + S_KB + off) = packbf(ra, rb);
            }
        }
    }

    // ================= out-proj (3-pass split), ring2 =================
    {
        float acc[4][4];
#pragma unroll
        for (int j = 0; j < 4; j++)
#pragma unroll
            for (int e = 0; e < 4; e++) acc[j][e] = 0.f;

#pragma unroll 1
        for (int kt = 0; kt < 8; kt++) {
            if (kt < 7) CP_WAIT1(); else CP_WAIT0();
            __syncthreads();                   // slab ready + attn-out visible

            uint32_t ah[4], al[4], bh[2][4], bl[2][4];
            uint32_t aoff = (uint32_t)((wm * 16 + lrow) * 272
                                       + kt * 32 + lhalf * 16);
            LDM4(ah, sb + aoff);               // attn-out hi (XH)
            LDM4(al, sb + S_KB + aoff);        // attn-out lo (KB)
            uint32_t pbase = sb + F_W + (kt & 1) * 9216 + (wn >> 1) * 4608;
#pragma unroll
            for (int nt = 0; nt < 2; nt++) {
                uint32_t boff = (uint32_t)(lrow * 144
                                + ((wn & 1) * 32 + nt * 16) * 2 + lhalf * 16);
                LDM4T(bh[nt], pbase + boff);
                LDM4T(bl[nt], pbase + 2304 + boff);
            }
#pragma unroll
            for (int j = 0; j < 4; j++)
                MMA_BF16(acc[j], ah, bh[j >> 1][2 * (j & 1)],
                         bh[j >> 1][2 * (j & 1) + 1]);
#pragma unroll
            for (int j = 0; j < 4; j++)
                MMA_BF16(acc[j], ah, bl[j >> 1][2 * (j & 1)],
                         bl[j >> 1][2 * (j & 1) + 1]);
#pragma unroll
            for (int j = 0; j < 4; j++)
                MMA_BF16(acc[j], al, bh[j >> 1][2 * (j & 1)],
                         bh[j >> 1][2 * (j & 1) + 1]);

            __syncthreads();                   // slot drained
            if (kt < 6) issue_vo(sb, kt & 1, kt + 2, t, 6);
        }

        const int r0 = wm * 16 + qrow, r1 = r0 + 8;
#pragma unroll
        for (int j = 0; j < 4; j++) {
            int col = wn * 32 + j * 8 + qt2;
            if (r0 < 49)
                *(float2*)(out + (win * WN + r0) * (size_t)D + col) =
                    make_float2(acc[j][0], acc[j][1]);
            if (r1 < 49)
                *(float2*)(out + (win * WN + r1) * (size_t)D + col) =
                    make_float2(acc[j][2], acc[j][3]);
        }
    }
}

// ============================== launcher ==============================
extern "C" void kernel_launch(void* const* d_in, const int* in_sizes, int n_in,
                              void* d_out, int out_size) {
    const float* x    = (const float*)d_in[0];
    const float* wqkv = (const float*)d_in[1];
    const float* wout = (const float*)d_in[2];
    const float* btab = (const float*)d_in[3];
    float* out = (float*)d_out;

    const int n_win = in_sizes[0] / (WN * D);

    cudaFuncSetAttribute(fused1,
                         cudaFuncAttributeMaxDynamicSharedMemorySize, F_TOTAL);

    prepack_w<<<256, 256>>>(wqkv, wout);
    fused1<<<n_win, 512, F_TOTAL>>>(x, btab, out);
}